// round 7
// baseline (speedup 1.0000x reference)
#include <cuda_runtime.h>
#include <cstdint>

// Problem constants
#define SIN   512          // input H=W
#define HW    128          // resized H=W and volume H=W
#define ND    128          // depth bins
#define NB    8            // batch
#define GUARD 4            // guard rows each side of the depth axis
#define AROWS (ND + 2*GUARD)   // 136 acc rows

// Scratch: per-pixel {xray_resized, (float)d_idx}
__device__ float2 g_pix[NB * HW * HW];

// ---------------------------------------------------------------------------
// Kernel A: jax.image.resize(bilinear, antialias) 512->128 for both arrays,
// fused with d_idx computation.  (R1 version, verbatim — measured ~5.5-6us)
// ---------------------------------------------------------------------------
__global__ __launch_bounds__(128) void resize_kernel(
    const float* __restrict__ depth, const float* __restrict__ xray)
{
    __shared__ float2 hrow[SIN];   // H-contracted row at this output row: {d, x}

    const int ho  = blockIdx.x;    // 0..127
    const int b   = blockIdx.y;    // 0..7
    const int tid = threadIdx.x;   // 128 threads

    const float BW[8] = {0.125f, 0.375f, 0.625f, 0.875f,
                         0.875f, 0.625f, 0.375f, 0.125f};

    const int ih0 = 4 * ho - 2;

    float whn[8]; float hs = 0.f;
    #pragma unroll
    for (int k = 0; k < 8; k++) {
        int ih = ih0 + k;
        float w = (ih >= 0 && ih < SIN) ? BW[k] : 0.f;
        whn[k] = w; hs += w;
    }
    #pragma unroll
    for (int k = 0; k < 8; k++) whn[k] = __fdiv_rn(whn[k], hs);

    const float* dbase = depth + (size_t)b * SIN * SIN;
    const float* xbase = xray  + (size_t)b * SIN * SIN;

    {
        const int c0 = tid * 4;
        float4 ad = make_float4(0.f, 0.f, 0.f, 0.f);
        float4 ax = make_float4(0.f, 0.f, 0.f, 0.f);
        #pragma unroll
        for (int kh = 0; kh < 8; kh++) {
            if (whn[kh] != 0.f) {
                const int ih = ih0 + kh;
                const float4 dv = *(const float4*)(dbase + (size_t)ih * SIN + c0);
                const float4 xv = *(const float4*)(xbase + (size_t)ih * SIN + c0);
                const float w = whn[kh];
                ad.x = fmaf(w, dv.x, ad.x); ad.y = fmaf(w, dv.y, ad.y);
                ad.z = fmaf(w, dv.z, ad.z); ad.w = fmaf(w, dv.w, ad.w);
                ax.x = fmaf(w, xv.x, ax.x); ax.y = fmaf(w, xv.y, ax.y);
                ax.z = fmaf(w, xv.z, ax.z); ax.w = fmaf(w, xv.w, ax.w);
            }
        }
        hrow[c0 + 0] = make_float2(ad.x, ax.x);
        hrow[c0 + 1] = make_float2(ad.y, ax.y);
        hrow[c0 + 2] = make_float2(ad.z, ax.z);
        hrow[c0 + 3] = make_float2(ad.w, ax.w);
    }
    __syncthreads();

    const int wo  = tid;
    const int iw0 = 4 * wo - 2;

    float wwn[8]; float ws = 0.f;
    #pragma unroll
    for (int k = 0; k < 8; k++) {
        int iw = iw0 + k;
        float w = (iw >= 0 && iw < SIN) ? BW[k] : 0.f;
        wwn[k] = w; ws += w;
    }
    #pragma unroll
    for (int k = 0; k < 8; k++) wwn[k] = __fdiv_rn(wwn[k], ws);

    float ad = 0.f, ax = 0.f;
    #pragma unroll
    for (int k = 0; k < 8; k++) {
        if (wwn[k] != 0.f) {
            float2 p = hrow[iw0 + k];
            ad = fmaf(wwn[k], p.x, ad);
            ax = fmaf(wwn[k], p.y, ax);
        }
    }

    // d_idx = clip(int32((d/100)*127), 0, 127) — IEEE ops to match reference
    float nd = __fdiv_rn(ad, 100.0f);
    int di = (int)__fmul_rn(nd, 127.0f);
    di = min(max(di, 0), ND - 1);

    g_pix[((size_t)b * HW + ho) * HW + wo] = make_float2(ax, (float)di);
}

// ---------------------------------------------------------------------------
// Kernel B (R5): guard-banded 5-tap gaussian splat, depth-box at writeout.
//   acc rows cover d = -4..131 (GUARD=4 each side). All taps stored
//   unconditionally; out-of-range taps land in guard rows never read back
//   (== reference's valid-mask drop). No bounds checks in the hot loop.
//   Same-parity taps are 1024B apart -> immediate-offset LDS/STS.
// ---------------------------------------------------------------------------
__global__ __launch_bounds__(256) void splat_pool_kernel(float* __restrict__ out)
{
    extern __shared__ float sm[];
    float*  acc = sm;                           // [136][128] = 69632B
    float2* pix = (float2*)(sm + AROWS * 128);  // [180] halo {x, d_idx}

    const int tid = threadIdx.x;        // 0..255
    const int w0  = blockIdx.x * 16;
    const int h0  = blockIdx.y * 8;
    const int b   = blockIdx.z;

    const float inv27 = 1.0f / 27.0f;
    const float W0 = 0.13533528323661270f * inv27;  // exp(-2)/27
    const float W1 = 0.60653065971263342f * inv27;  // exp(-0.5)/27
    const float W2 = inv27;                         // exp(0)/27

    // Zero only the live rows d=0..127 (guard rows are never read).
    {
        float4* a4 = (float4*)(acc + GUARD * 128);
        #pragma unroll
        for (int i = tid; i < 4096; i += 256)
            a4[i] = make_float4(0.f, 0.f, 0.f, 0.f);
    }
    // Stage the 10x18 halo pixel map
    if (tid < 180) {
        const int ph = h0 + tid / 18 - 1;
        const int pw = w0 + tid % 18 - 1;
        float2 q = make_float2(0.f, 64.f);
        if (ph >= 0 && ph < HW && pw >= 0 && pw < HW)
            q = g_pix[((size_t)b * HW + ph) * HW + pw];
        pix[tid] = q;
    }
    __syncthreads();

    // Splat: 9 neighbors x 5 gaussian taps, parity-split over d (no races),
    // unconditional stores into the guard-banded accumulator.
    {
        const int p  = tid >> 7;        // depth parity this thread owns
        const int ct = tid & 127;       // column within 8x16 tile
        const int ty = ct >> 4;         // 0..7
        const int tx = ct & 15;         // 0..15

        // Preload the 9 neighbor pixels into registers.
        float xn[9]; int dsn[9];
        #pragma unroll
        for (int dh = 0; dh < 3; dh++)
            #pragma unroll
            for (int dw = 0; dw < 3; dw++) {
                const float2 q = pix[(ty + dh) * 18 + (tx + dw)];
                xn[dh * 3 + dw]  = q.x;
                dsn[dh * 3 + dw] = (int)q.y - 2;   // first tap depth
            }

        #pragma unroll
        for (int n = 0; n < 9; n++) {
            const int   ds = dsn[n];
            const float x  = xn[n];
            const int   ks = (p - ds) & 1;          // first tap of my parity
            // taps k = ks, ks+2, ks+4 (third only when ks==0)
            const float wa = ks ? W1 : W0;          // Wt[ks]
            const float wb = ks ? W1 : W2;          // Wt[ks+2]
            float* base = &acc[(ds + GUARD + ks) * 128 + ct];
            const float a0 = base[0];
            const float a1 = base[256];
            base[0]   = fmaf(x, wa, a0);
            base[256] = fmaf(x, wb, a1);
            if (ks == 0) {
                const float a2 = base[512];
                base[512] = fmaf(x, W0, a2);        // Wt[4]
            }
        }
    }
    __syncthreads();

    // Writeout: 3-tap running sum over d, float4 across 4 columns.
    // 32 column-groups x 8 d-chunks of 16 = 256 threads.
    {
        const int g  = tid & 31;         // column group (4 cols)
        const int dc = tid >> 5;         // d-chunk 0..7
        const int d0 = dc * 16;
        const int oy = (g * 4) >> 4;     // 0..7
        const int ox = (g * 4) & 15;     // 0,4,8,12
        const float4* a4 = (const float4*)acc;   // [136 rows][32 groups]

        float4 vm1 = (d0 == 0) ? make_float4(0.f, 0.f, 0.f, 0.f)
                               : a4[(d0 - 1 + GUARD) * 32 + g];
        float4 v0  = a4[(d0 + GUARD) * 32 + g];
        const size_t obase =
            (((size_t)b * ND) * HW + (h0 + oy)) * HW + w0 + ox;
        #pragma unroll
        for (int i = 0; i < 16; i++) {
            const int d = d0 + i;
            float4 vp1 = (d == ND - 1) ? make_float4(0.f, 0.f, 0.f, 0.f)
                                       : a4[(d + 1 + GUARD) * 32 + g];
            float4 o;
            o.x = vm1.x + v0.x + vp1.x;
            o.y = vm1.y + v0.y + vp1.y;
            o.z = vm1.z + v0.z + vp1.z;
            o.w = vm1.w + v0.w + vp1.w;
            *(float4*)&out[obase + (size_t)d * HW * HW] = o;
            vm1 = v0; v0 = vp1;
        }
    }
}

// ---------------------------------------------------------------------------
extern "C" void kernel_launch(void* const* d_in, const int* in_sizes, int n_in,
                              void* d_out, int out_size)
{
    const float* depth = (const float*)d_in[0];
    const float* xray  = (const float*)d_in[1];
    float* out = (float*)d_out;

    // Kernel A: resize + d_idx
    resize_kernel<<<dim3(HW, NB), 128>>>(depth, xray);

    // Kernel B: splat + 3x3x3 box average
    const int smem_b = AROWS * 128 * (int)sizeof(float) + 180 * (int)sizeof(float2);
    cudaFuncSetAttribute(splat_pool_kernel,
                         cudaFuncAttributeMaxDynamicSharedMemorySize, smem_b);
    splat_pool_kernel<<<dim3(HW / 16, HW / 8, NB), 256, smem_b>>>(out);
}

// round 8
// speedup vs baseline: 1.1664x; 1.1664x over previous
#include <cuda_runtime.h>
#include <cstdint>

// Problem constants
#define SIN   512          // input H=W
#define HW    128          // resized H=W and volume H=W
#define ND    128          // depth bins
#define NB    8            // batch
#define GUARD 4            // guard rows each side of the depth axis
#define AROWS (ND + 2*GUARD)   // 136 acc rows

// Scratch: per-pixel {xray_resized, (float)d_idx}
__device__ float2 g_pix[NB * HW * HW];

// ---------------------------------------------------------------------------
// Kernel A: jax.image.resize(bilinear, antialias) 512->128 for both arrays,
// fused with d_idx computation.  (R1 version, verbatim)
// ---------------------------------------------------------------------------
__global__ __launch_bounds__(128) void resize_kernel(
    const float* __restrict__ depth, const float* __restrict__ xray)
{
    __shared__ float2 hrow[SIN];   // H-contracted row at this output row: {d, x}

    const int ho  = blockIdx.x;    // 0..127
    const int b   = blockIdx.y;    // 0..7
    const int tid = threadIdx.x;   // 128 threads

    const float BW[8] = {0.125f, 0.375f, 0.625f, 0.875f,
                         0.875f, 0.625f, 0.375f, 0.125f};

    const int ih0 = 4 * ho - 2;

    float whn[8]; float hs = 0.f;
    #pragma unroll
    for (int k = 0; k < 8; k++) {
        int ih = ih0 + k;
        float w = (ih >= 0 && ih < SIN) ? BW[k] : 0.f;
        whn[k] = w; hs += w;
    }
    #pragma unroll
    for (int k = 0; k < 8; k++) whn[k] = __fdiv_rn(whn[k], hs);

    const float* dbase = depth + (size_t)b * SIN * SIN;
    const float* xbase = xray  + (size_t)b * SIN * SIN;

    {
        const int c0 = tid * 4;
        float4 ad = make_float4(0.f, 0.f, 0.f, 0.f);
        float4 ax = make_float4(0.f, 0.f, 0.f, 0.f);
        #pragma unroll
        for (int kh = 0; kh < 8; kh++) {
            if (whn[kh] != 0.f) {
                const int ih = ih0 + kh;
                const float4 dv = *(const float4*)(dbase + (size_t)ih * SIN + c0);
                const float4 xv = *(const float4*)(xbase + (size_t)ih * SIN + c0);
                const float w = whn[kh];
                ad.x = fmaf(w, dv.x, ad.x); ad.y = fmaf(w, dv.y, ad.y);
                ad.z = fmaf(w, dv.z, ad.z); ad.w = fmaf(w, dv.w, ad.w);
                ax.x = fmaf(w, xv.x, ax.x); ax.y = fmaf(w, xv.y, ax.y);
                ax.z = fmaf(w, xv.z, ax.z); ax.w = fmaf(w, xv.w, ax.w);
            }
        }
        hrow[c0 + 0] = make_float2(ad.x, ax.x);
        hrow[c0 + 1] = make_float2(ad.y, ax.y);
        hrow[c0 + 2] = make_float2(ad.z, ax.z);
        hrow[c0 + 3] = make_float2(ad.w, ax.w);
    }
    __syncthreads();

    const int wo  = tid;
    const int iw0 = 4 * wo - 2;

    float wwn[8]; float ws = 0.f;
    #pragma unroll
    for (int k = 0; k < 8; k++) {
        int iw = iw0 + k;
        float w = (iw >= 0 && iw < SIN) ? BW[k] : 0.f;
        wwn[k] = w; ws += w;
    }
    #pragma unroll
    for (int k = 0; k < 8; k++) wwn[k] = __fdiv_rn(wwn[k], ws);

    float ad = 0.f, ax = 0.f;
    #pragma unroll
    for (int k = 0; k < 8; k++) {
        if (wwn[k] != 0.f) {
            float2 p = hrow[iw0 + k];
            ad = fmaf(wwn[k], p.x, ad);
            ax = fmaf(wwn[k], p.y, ax);
        }
    }

    // d_idx = clip(int32((d/100)*127), 0, 127) — IEEE ops to match reference
    float nd = __fdiv_rn(ad, 100.0f);
    int di = (int)__fmul_rn(nd, 127.0f);
    di = min(max(di, 0), ND - 1);

    g_pix[((size_t)b * HW + ho) * HW + wo] = make_float2(ax, (float)di);
}

// ---------------------------------------------------------------------------
// Kernel B (R8): guard-banded 5-tap gaussian splat + depth-box at writeout,
// now RANGE-ADAPTIVE: the block reduces min/max d_idx over its halo and
//   - zeroes only acc rows [smin-4, smax+4]
//   - writeout: outputs outside [smin-3, smax+3] are STG-zero (no LDS);
//     inside, the rolling 3-tap sum (all rows read are inside the zeroed
//     range by construction).
// Correct for any input; fast when the depth histogram is narrow.
// ---------------------------------------------------------------------------
__global__ __launch_bounds__(256) void splat_pool_kernel(float* __restrict__ out)
{
    extern __shared__ float sm[];
    float*  acc    = sm;                           // [136][128] = 69632B
    float2* pix    = (float2*)(sm + AROWS * 128);  // [180] halo {x, d_idx}
    int*    srange = (int*)(pix + 180);            // [0]=min di, [1]=max di

    const int tid = threadIdx.x;        // 0..255
    const int w0  = blockIdx.x * 16;
    const int h0  = blockIdx.y * 8;
    const int b   = blockIdx.z;

    const float inv27 = 1.0f / 27.0f;
    const float W0 = 0.13533528323661270f * inv27;  // exp(-2)/27
    const float W1 = 0.60653065971263342f * inv27;  // exp(-0.5)/27
    const float W2 = inv27;                         // exp(0)/27
    const float4 z4 = make_float4(0.f, 0.f, 0.f, 0.f);

    // Phase A: stage halo pixels; init range.
    float2 q = make_float2(0.f, 64.f);
    bool valid = false;
    if (tid < 180) {
        const int ph = h0 + tid / 18 - 1;
        const int pw = w0 + tid % 18 - 1;
        if (ph >= 0 && ph < HW && pw >= 0 && pw < HW) {
            q = g_pix[((size_t)b * HW + ph) * HW + pw];
            valid = true;
        }
        pix[tid] = q;
    }
    if (tid == 0) { srange[0] = ND - 1; srange[1] = 0; }
    __syncthreads();

    // Phase B: min/max reduction over valid halo d_idx.
    if (valid) {
        const int di = (int)q.y;
        atomicMin(&srange[0], di);
        atomicMax(&srange[1], di);
    }
    __syncthreads();

    const int smin = srange[0], smax = srange[1];

    // Phase C: zero only rows d in [smin-4, smax+4] (clipped).
    {
        const int zlo = max(0, smin - 4);
        const int zhi = min(ND - 1, smax + 4);
        const int nz  = (zhi - zlo + 1) * 32;       // float4 count
        float4* a4 = (float4*)(acc + (zlo + GUARD) * 128);
        for (int i = tid; i < nz; i += 256) a4[i] = z4;
    }
    __syncthreads();

    // Phase D: splat — 9 neighbors x 5 gaussian taps, parity-split over d,
    // unconditional stores into the guard-banded accumulator.
    {
        const int p  = tid >> 7;        // depth parity this thread owns
        const int ct = tid & 127;       // column within 8x16 tile
        const int ty = ct >> 4;         // 0..7
        const int tx = ct & 15;         // 0..15

        float xn[9]; int dsn[9];
        #pragma unroll
        for (int dh = 0; dh < 3; dh++)
            #pragma unroll
            for (int dw = 0; dw < 3; dw++) {
                const float2 qq = pix[(ty + dh) * 18 + (tx + dw)];
                xn[dh * 3 + dw]  = qq.x;
                dsn[dh * 3 + dw] = (int)qq.y - 2;   // first tap depth
            }

        #pragma unroll
        for (int n = 0; n < 9; n++) {
            const int   ds = dsn[n];
            const float x  = xn[n];
            const int   ks = (p - ds) & 1;          // first tap of my parity
            const float wa = ks ? W1 : W0;          // Wt[ks]
            const float wb = ks ? W1 : W2;          // Wt[ks+2]
            float* base = &acc[(ds + GUARD + ks) * 128 + ct];
            const float a0 = base[0];
            const float a1 = base[256];
            base[0]   = fmaf(x, wa, a0);
            base[256] = fmaf(x, wb, a1);
            if (ks == 0) {
                const float a2 = base[512];
                base[512] = fmaf(x, W0, a2);        // Wt[4]
            }
        }
    }
    __syncthreads();

    // Phase E: writeout. Outputs outside [smin-3, smax+3] are zero.
    {
        const int olo = max(0, smin - 3);
        const int ohi = min(ND - 1, smax + 3);

        const int g  = tid & 31;         // column group (4 cols)
        const int dc = tid >> 5;         // d-chunk 0..7
        const int d0 = dc * 16;
        const int oy = (g * 4) >> 4;     // 0..7
        const int ox = (g * 4) & 15;     // 0,4,8,12
        const float4* a4 = (const float4*)acc;   // [136 rows][32 groups]

        const size_t obase =
            (((size_t)b * ND) * HW + (h0 + oy)) * HW + w0 + ox;

        const int a  = max(d0, olo);
        const int bq = min(d0 + 15, ohi);

        if (a > bq) {
            for (int d = d0; d < d0 + 16; d++)
                *(float4*)&out[obase + (size_t)d * HW * HW] = z4;
        } else {
            for (int d = d0; d < a; d++)
                *(float4*)&out[obase + (size_t)d * HW * HW] = z4;

            float4 vm1 = (a == 0) ? z4 : a4[(a - 1 + GUARD) * 32 + g];
            float4 v0  = a4[(a + GUARD) * 32 + g];
            for (int d = a; d <= bq; d++) {
                float4 vp1 = (d == ND - 1) ? z4 : a4[(d + 1 + GUARD) * 32 + g];
                float4 o;
                o.x = vm1.x + v0.x + vp1.x;
                o.y = vm1.y + v0.y + vp1.y;
                o.z = vm1.z + v0.z + vp1.z;
                o.w = vm1.w + v0.w + vp1.w;
                *(float4*)&out[obase + (size_t)d * HW * HW] = o;
                vm1 = v0; v0 = vp1;
            }

            for (int d = bq + 1; d < d0 + 16; d++)
                *(float4*)&out[obase + (size_t)d * HW * HW] = z4;
        }
    }
}

// ---------------------------------------------------------------------------
extern "C" void kernel_launch(void* const* d_in, const int* in_sizes, int n_in,
                              void* d_out, int out_size)
{
    const float* depth = (const float*)d_in[0];
    const float* xray  = (const float*)d_in[1];
    float* out = (float*)d_out;

    // Kernel A: resize + d_idx
    resize_kernel<<<dim3(HW, NB), 128>>>(depth, xray);

    // Kernel B: splat + 3x3x3 box average (range-adaptive)
    const int smem_b = AROWS * 128 * (int)sizeof(float)
                     + 180 * (int)sizeof(float2) + 2 * (int)sizeof(int);
    cudaFuncSetAttribute(splat_pool_kernel,
                         cudaFuncAttributeMaxDynamicSharedMemorySize, smem_b);
    splat_pool_kernel<<<dim3(HW / 16, HW / 8, NB), 256, smem_b>>>(out);
}